// round 15
// baseline (speedup 1.0000x reference)
#include <cuda_runtime.h>
#include <math.h>
#include <stdint.h>

#define NB    64
#define N0    1083     // 3*19*19
#define N1    4332     // 3*38*38
#define N2    17328    // 3*76*76
#define NTOT  22743
#define MCAND 256
#define NEGV  (-1e9f)
#define NMS_T 0.1f

#define RPB   256                         // records per score block
#define NBLK0 ((NB * N0 + RPB - 1) / RPB) // 271 (last block 192 records, even)
#define NBLK1 ((NB * N1) / RPB)           // 1083 (exact)
#define NBLK2 ((NB * N2) / RPB)           // 4332 (exact)
#define NSBLK (NBLK0 + NBLK1 + NBLK2)     // 5686 scoring blocks

// scratch (static __device__ — zero-init at load; counters reset per call by consumer blocks)
__device__ int    g_done [NB];         // scoring blocks finished for image b
__device__ int    g_ncand[NB];
__device__ float  g_vsc [NB * NTOT];   // candidate scores per image
__device__ float4 g_cbx [NB * NTOT];   // candidate decoded boxes (xyxy, clamped)
__device__ float  g_car [NB * NTOT];   // candidate areas (+1 convention)
__device__ int    g_ccl [NB * NTOT];   // candidate class ids

__device__ __forceinline__ unsigned redux_umax(unsigned v) {
    unsigned r; asm("redux.sync.max.u32 %0, %1, 0xffffffff;" : "=r"(r) : "r"(v)); return r;
}
__device__ __forceinline__ unsigned redux_umin(unsigned v) {
    unsigned r; asm("redux.sync.min.u32 %0, %1, 0xffffffff;" : "=r"(r) : "r"(v)); return r;
}
__device__ __forceinline__ uint32_t smem_u32(const void* p) {
    return (uint32_t)__cvta_generic_to_shared(p);
}
__device__ __forceinline__ void mbar_wait_p0(uint32_t mb) {
    asm volatile(
        "{\n\t"
        ".reg .pred P1;\n\t"
        "WAIT_%=:\n\t"
        "mbarrier.try_wait.parity.shared.b64 P1, [%0], 0;\n\t"
        "@P1 bra.uni DONE_%=;\n\t"
        "bra.uni WAIT_%=;\n\t"
        "DONE_%=:\n\t"
        "}"
        :: "r"(mb) : "memory");
}

// geometry for flat per-image index n
__device__ __forceinline__ void geom(int n, int& gx, int& gy,
                                     float& stride, float& aw, float& ah)
{
    if (n < N0) {
        int a = n / 361, c = n - a * 361; gy = c / 19; gx = c - gy * 19;
        stride = 32.0f;
        aw = (a == 0) ? 116.0f : (a == 1) ? 156.0f : 373.0f;
        ah = (a == 0) ?  90.0f : (a == 1) ? 198.0f : 326.0f;
    } else if (n < N0 + N1) {
        int r = n - N0;
        int a = r / 1444, c = r - a * 1444; gy = c / 38; gx = c - gy * 38;
        stride = 16.0f;
        aw = (a == 0) ? 30.0f : (a == 1) ? 62.0f : 59.0f;
        ah = (a == 0) ? 61.0f : (a == 1) ? 45.0f : 119.0f;
    } else {
        int r = n - N0 - N1;
        int a = r / 5776, c = r - a * 5776; gy = c / 76; gx = c - gy * 76;
        stride = 8.0f;
        aw = (a == 0) ? 10.0f : (a == 1) ? 16.0f : 33.0f;
        ah = (a == 0) ? 13.0f : (a == 1) ? 30.0f : 23.0f;
    }
}

// blocks of a level touching image b (RPB=256)
__device__ __forceinline__ int blocks_touching(int NL, int b) {
    int first = (b * NL) / RPB;
    int last  = ((b + 1) * NL - 1) / RPB;
    return last - first + 1;
}

struct SmemScore {
    alignas(16) float sm[RPB * 26];
    alignas(8) unsigned long long mbar;
    unsigned short s_list[RPB];
    int s_cnt;
};
struct SmemRest {
    unsigned hist[2048];
    unsigned wtot[8], wsuf[8];
    int sh_chosen, sh_need, sh_abv, sh_nG, cntG, cntE;
    unsigned lval[MCAND];
    int      lidx[MCAND];
    int      s_idx[MCAND];
    float    ssc [MCAND];
    float4   sb  [MCAND];
    float    sa  [MCAND];
    int      scl [MCAND];
    int      cs  [20 * 32];
    unsigned skept[8];
};

// =============================== scoring role ===============================
__device__ void score_block(int blk, const float* __restrict__ l0,
                            const float* __restrict__ l1, const float* __restrict__ l2,
                            SmemScore* S)
{
    const float* in; int NL, OFF, base;
    if (blk < NBLK0)              { in = l0; NL = N0; OFF = 0;       base = blk * RPB; }
    else if (blk < NBLK0 + NBLK1) { in = l1; NL = N1; OFF = N0;      base = (blk - NBLK0) * RPB; }
    else                          { in = l2; NL = N2; OFF = N0 + N1; base = (blk - NBLK0 - NBLK1) * RPB; }

    int total = NB * NL;
    int nrec  = total - base; if (nrec > RPB) nrec = RPB;
    unsigned bytes = (unsigned)nrec * 104u;      // multiple of 16 (nrec even)
    const float* __restrict__ src = in + (size_t)base * 26;

    uint32_t mb = smem_u32(&S->mbar);
    if (threadIdx.x == 0) {
        S->s_cnt = 0;
        asm volatile("mbarrier.init.shared.b64 [%0], 1;" :: "r"(mb) : "memory");
    }
    __syncthreads();
    if (threadIdx.x == 0) {
        asm volatile("mbarrier.arrive.expect_tx.shared.b64 _, [%0], %1;"
                     :: "r"(mb), "r"(bytes) : "memory");
        asm volatile("cp.async.bulk.shared::cta.global.mbarrier::complete_tx::bytes "
                     "[%0], [%1], %2, [%3];"
                     :: "r"(smem_u32(S->sm)), "l"(src), "r"(bytes), "r"(mb) : "memory");
    }
    mbar_wait_p0(mb);

    int t = threadIdx.x;
    unsigned lane = t & 31u;
    bool pass = false;
    if (t < nrec) {
        float p4 = S->sm[t * 26 + 4], p5 = S->sm[t * 26 + 5];
        // obj>=0.6 <=> p4>=ln(1.5); loc>=0.5 <=> p5>=0 (conservative; exact test below)
        pass = (p4 >= 0.405f) && (p5 >= -1e-6f);
    }
    unsigned mball = __ballot_sync(0xffffffffu, pass);
    int bs = 0;
    if (mball) {
        if (lane == 0) bs = atomicAdd(&S->s_cnt, __popc(mball));
        bs = __shfl_sync(0xffffffffu, bs, 0);
        if (pass) S->s_list[bs + __popc(mball & ((1u << lane) - 1u))] = (unsigned short)t;
    }
    __syncthreads();
    int cnt = S->s_cnt;

    int b_first = base / NL;
    int rem     = base - b_first * NL;
    int b_last  = (base + nrec - 1) / NL;

    bool valid = false;
    float score = 0.0f;
    int bimg = 0, nloc = 0;
    float4 bx = make_float4(0.f, 0.f, 0.f, 0.f);
    int cc = 0;
    if (t < cnt) {
        int rec = S->s_list[t];
        const float* p = S->sm + rec * 26;
        float obj = 1.0f / (1.0f + expf(-p[4]));
        float loc = 1.0f / (1.0f + expf(-p[5]));
        float m = p[6];
#pragma unroll
        for (int i = 1; i < 20; i++) m = fmaxf(m, p[6 + i]);
        float s = 0.0f;
#pragma unroll
        for (int i = 0; i < 20; i++) s += expf(p[6 + i] - m);
        float conf = 1.0f / s;
        valid = (obj >= 0.6f) && (obj * conf >= 0.05f) && (loc >= 0.5f);
        score = sqrtf(obj * conf) * sqrtf(loc);
        int r_off = rec + rem;
        int over  = (r_off >= NL);
        bimg = b_first + over;
        nloc = r_off - (over ? NL : 0);

        if (valid) {
            int gx, gy; float stride, aw, ah;
            geom(OFF + nloc, gx, gy, stride, aw, ah);
            float cx = (1.0f / (1.0f + expf(-p[0])) + (float)gx) * stride;
            float cy = (1.0f / (1.0f + expf(-p[1])) + (float)gy) * stride;
            float w  = expf(p[2]) * aw;
            float h  = expf(p[3]) * ah;
            bx.x = fminf(fmaxf(cx - w * 0.5f, 0.0f), 608.0f);
            bx.y = fminf(fmaxf(cy - h * 0.5f, 0.0f), 608.0f);
            bx.z = fminf(fmaxf(cx + w * 0.5f, 0.0f), 608.0f);
            bx.w = fminf(fmaxf(cy + h * 0.5f, 0.0f), 608.0f);
            float best = p[6]; cc = 0;
#pragma unroll
            for (int i = 1; i < 20; i++) {
                float v = p[6 + i];
                if (v > best) { best = v; cc = i; }   // first max, like jnp.argmax
            }
        }
    }

    // warp-aggregated append (survivors in a warp span at most 2 images)
    int b0 = __shfl_sync(0xffffffffu, bimg, 0);
    bool same = (bimg == b0);
    unsigned m_same = __ballot_sync(0xffffffffu, valid && same);
    unsigned m_diff = __ballot_sync(0xffffffffu, valid && !same);
    int pos = -1, bw = 0;
    if (m_same) {
        int leader = __ffs(m_same) - 1;
        int base2 = 0;
        if ((int)lane == leader) base2 = atomicAdd(&g_ncand[b0], __popc(m_same));
        base2 = __shfl_sync(0xffffffffu, base2, leader);
        if (valid && same) { pos = base2 + __popc(m_same & ((1u << lane) - 1u)); bw = b0; }
    }
    if (m_diff) {
        int leader = __ffs(m_diff) - 1;
        int b1 = __shfl_sync(0xffffffffu, bimg, leader);
        int base2 = 0;
        if ((int)lane == leader) base2 = atomicAdd(&g_ncand[b1], __popc(m_diff));
        base2 = __shfl_sync(0xffffffffu, base2, leader);
        if (valid && !same) { pos = base2 + __popc(m_diff & ((1u << lane) - 1u)); bw = b1; }
    }
    if (pos >= 0) {
        size_t g = (size_t)bw * NTOT + pos;
        g_vsc[g] = score;
        g_cbx[g] = bx;
        g_car[g] = (bx.z - bx.x + 1.0f) * (bx.w - bx.y + 1.0f);
        g_ccl[g] = cc;
    }

    // release: all appends visible, then signal touched images
    __syncthreads();
    if (threadIdx.x == 0) {
        __threadfence();
        atomicAdd(&g_done[b_first], 1);
        if (b_last != b_first) atomicAdd(&g_done[b_last], 1);
    }
}

// =============================== consumer role ===============================
__device__ void rest_block(int b, float* __restrict__ out, SmemRest* R)
{
    int tid = threadIdx.x;
    const int nth = 256;
    int wid = tid >> 5, lane = tid & 31;

    // prologue overlaps the spin target's production
    for (int i = tid; i < MCAND; i += nth) { R->s_idx[i] = -1; R->ssc[i] = NEGV; }
    for (int i = tid; i < 2048; i += nth) R->hist[i] = 0u;
    if (tid < 8) R->skept[tid] = 0u;
    if (tid == 0) { R->sh_need = MCAND; R->cntG = 0; R->cntE = 0; }

    // acquire: wait until every scoring block touching image b has signaled
    int expected = blocks_touching(N0, b) + blocks_touching(N1, b) + blocks_touching(N2, b);
    if (tid == 0) {
        while (atomicAdd(&g_done[b], 0) < expected) __nanosleep(128);
        __threadfence();
    }
    __syncthreads();

    int n = g_ncand[b];
    const float* __restrict__ vs = g_vsc + (size_t)b * NTOT;
    __syncthreads();
    if (tid == 0) { g_ncand[b] = 0; g_done[b] = 0; }   // reset for next replay

    if (n <= MCAND) {
        for (int i = tid; i < n; i += nth) { R->s_idx[i] = i; R->ssc[i] = vs[i]; }
    } else {
        // 11-bit histogram over key bits [14:25): valid scores in [0.158,1.0]
        // => key bits [25:32) == 0x1F constant
        for (int i = tid; i < n; i += nth) {
            unsigned k = __float_as_uint(vs[i]);
            atomicAdd(&R->hist[(k >> 14) & 2047u], 1u);
        }
        __syncthreads();

        unsigned loc[8], tot = 0, ssum = 0;
        {
#pragma unroll
            for (int j = 7; j >= 0; j--) { tot += R->hist[tid * 8 + j]; loc[j] = tot; }
            ssum = tot;
#pragma unroll
            for (int off = 1; off < 32; off <<= 1) {
                unsigned o = __shfl_down_sync(0xffffffffu, ssum, off);
                if (lane + off < 32) ssum += o;
            }
            if (lane == 0) R->wtot[wid] = ssum;
        }
        __syncthreads();
        if (tid == 0) {
            unsigned run = 0;
            for (int w = 7; w >= 0; w--) { R->wsuf[w] = run; run += R->wtot[w]; }
        }
        __syncthreads();
        {
            unsigned above_t = R->wsuf[wid] + (ssum - tot);
#pragma unroll
            for (int j = 0; j < 8; j++) {
                unsigned sj  = above_t + loc[j];
                unsigned sj1 = (j == 7) ? above_t : above_t + loc[j + 1];
                if ((int)sj >= MCAND && (int)sj1 < MCAND) { R->sh_chosen = tid * 8 + j; R->sh_nG = (int)sj1; }
            }
        }
        __syncthreads();

        int nG      = R->sh_nG;
        int need2   = MCAND - nG;
        int cntbin  = (int)R->hist[R->sh_chosen];
        unsigned Pfull = (0x1Fu << 11) | (unsigned)R->sh_chosen;

        if (cntbin <= MCAND) {
            for (int i = tid; i < n; i += nth) {
                float v = vs[i];
                unsigned k = __float_as_uint(v);
                unsigned hi = k >> 14;
                if (hi > Pfull) {
                    int pos = atomicAdd(&R->cntG, 1);
                    R->s_idx[pos] = i; R->ssc[pos] = v;
                } else if (hi == Pfull) {
                    int e = atomicAdd(&R->cntE, 1);
                    R->lval[e] = k; R->lidx[e] = i;
                }
            }
            __syncthreads();
            if (wid == 0) {
                unsigned v0[8]; int id0[8];
#pragma unroll
                for (int j = 0; j < 8; j++) {
                    int p = lane + 32 * j;
                    v0[j]  = (p < cntbin) ? R->lval[p] : 0u;
                    id0[j] = (p < cntbin) ? R->lidx[p] : -1;
                }
                for (int r = 0; r < need2; r++) {
                    unsigned lm = v0[0];
#pragma unroll
                    for (int j = 1; j < 8; j++) lm = (v0[j] > lm) ? v0[j] : lm;
                    unsigned wm = redux_umax(lm);
                    unsigned li = 0xFFFFFFFFu;
                    if (lm == wm) {
#pragma unroll
                        for (int j = 7; j >= 0; j--)
                            if (v0[j] == wm) li = (unsigned)(lane + 32 * j);
                    }
                    unsigned wi = redux_umin(li);
                    if ((wi & 31u) == (unsigned)lane) {
                        int j = (int)(wi >> 5);
                        R->s_idx[nG + r] = id0[j];
                        R->ssc [nG + r] = __uint_as_float(v0[j]);
                        v0[j] = 0u;
                    }
                }
            }
        } else {
            // fallback (cntbin > 256, ~never): proven 4x8-bit radix
            unsigned prefix = 0;
            for (int p = 0; p < 4; p++) {
                if (tid < 256) R->hist[tid] = 0;
                __syncthreads();
                int shift = 24 - 8 * p;
                for (int i = tid; i < n; i += nth) {
                    unsigned k = __float_as_uint(vs[i]);
                    if (p == 0 || (k >> (shift + 8)) == prefix)
                        atomicAdd(&R->hist[(k >> shift) & 255u], 1u);
                }
                __syncthreads();
                int need = R->sh_need;
                if (tid < 32) {
                    unsigned lc[8]; unsigned tt = 0;
#pragma unroll
                    for (int j = 7; j >= 0; j--) { tt += R->hist[tid * 8 + j]; lc[j] = tt; }
                    unsigned s = tt;
#pragma unroll
                    for (int off = 1; off < 32; off <<= 1) {
                        unsigned o = __shfl_down_sync(0xffffffffu, s, off);
                        if (tid + off < 32) s += o;
                    }
                    unsigned above = s - tt;
#pragma unroll
                    for (int j = 0; j < 8; j++) {
                        unsigned sj  = above + lc[j];
                        unsigned sj1 = (j == 7) ? above : above + lc[j + 1];
                        if ((int)sj >= need && (int)sj1 < need) {
                            R->sh_chosen = tid * 8 + j; R->sh_abv = (int)sj1;
                        }
                    }
                }
                __syncthreads();
                if (tid == 0) R->sh_need = need - R->sh_abv;
                __syncthreads();
                prefix = (prefix << 8) | (unsigned)R->sh_chosen;
            }
            int need = R->sh_need;
            unsigned K = prefix;
            int nG2 = MCAND - need;
            for (int i = tid; i < n; i += nth) {
                float v = vs[i];
                unsigned k = __float_as_uint(v);
                int pos = -1;
                if (k > K)       pos = atomicAdd(&R->cntG, 1);
                else if (k == K) { int e = atomicAdd(&R->cntE, 1); if (e < need) pos = nG2 + e; }
                if (pos >= 0) { R->s_idx[pos] = i; R->ssc[pos] = v; }
            }
        }
    }
    __syncthreads();

    // gather precomputed decode data (24B per candidate)
    {
        int idx = R->s_idx[tid];
        float4 bx = make_float4(0.f, 0.f, 0.f, 0.f);
        float ar = 1.0f;
        int cc = -1;
        if (idx >= 0) {
            size_t g = (size_t)b * NTOT + idx;
            bx = g_cbx[g];
            ar = g_car[g];
            cc = g_ccl[g];
        }
        R->sb [tid] = bx;
        R->sa [tid] = ar;
        R->scl[tid] = cc;
    }
    __syncthreads();

    // per-class soft-NMS: 8 warps, warp w handles classes {w, w+8, w+16}
    // (kept set decomposes exactly per class; per-class compaction puts one
    // candidate per lane)
    for (int cl = wid; cl < 20; cl += 8) {
        int m = 0;
#pragma unroll
        for (int j = 0; j < 8; j++) {              // slots in increasing order
            int slot = j * 32 + lane;
            bool a = (R->scl[slot] == cl);
            unsigned mj = __ballot_sync(0xffffffffu, a);
            if (a) {
                int pos = m + __popc(mj & ((1u << lane) - 1u));
                if (pos < 32) R->cs[cl * 32 + pos] = slot;
            }
            m += __popc(mj);
        }
        __syncwarp();

        if (m > 0 && m <= 32) {
            bool active = lane < m;
            int slot = active ? R->cs[cl * 32 + lane] : 0;
            float4 B = R->sb[slot];
            float A2 = R->sa[slot];
            float sc = R->ssc[slot];
            unsigned key = active ? __float_as_uint(sc) : 0u;
            for (int it = 0; it < MCAND; it++) {
                unsigned wm = redux_umax(key);
                if (__uint_as_float(wm) < NMS_T) break;   // includes wm==0
                unsigned li = (key == wm) ? (unsigned)slot : 0xFFFFFFFFu;
                unsigned wi = redux_umin(li);             // first-index tie-break (exact)
                float4 wb = R->sb[wi];
                float  a1 = R->sa[wi];
                bool winner = active && ((unsigned)slot == wi);
                if (active) {
                    float ix1 = fmaxf(wb.x, B.x), iy1 = fmaxf(wb.y, B.y);
                    float ix2 = fminf(wb.z, B.z), iy2 = fminf(wb.w, B.w);
                    float iw = ix2 - ix1 + 1.0f, ih = iy2 - iy1 + 1.0f;
                    // inter==0 => decay=1.0 => sc unchanged (bitwise exact) — skip
                    if (iw > 0.0f && ih > 0.0f) {
                        float inter = iw * ih;
                        float iou = inter / (a1 + A2 - inter + 1e-16f);
                        sc *= expf(-(iou * iou) * 2.0f);   // exp(-iou^2 / 0.5)
                        key = __float_as_uint(sc);
                    }
                }
                if (winner) {
                    key = 0u; active = false;
                    atomicOr(&R->skept[slot >> 5], 1u << (slot & 31));
                }
            }
        } else if (m > 32) {
            // rare fallback: 8-slot register loop (exact)
            unsigned key[8]; float sc[8]; float4 bx[8]; float a2[8]; bool act[8];
#pragma unroll
            for (int j = 0; j < 8; j++) {
                int slot = j * 32 + lane;
                float s = R->ssc[slot];
                act[j] = (R->scl[slot] == cl);
                key[j] = act[j] ? __float_as_uint(s) : 0u;
                sc[j]  = s;
                bx[j]  = R->sb[slot];
                a2[j]  = R->sa[slot];
            }
            unsigned keptloc = 0;
            for (int it = 0; it < MCAND; it++) {
                unsigned lm = 0, li = 0;
#pragma unroll
                for (int j = 0; j < 8; j++)
                    if (key[j] > lm) { lm = key[j]; li = (unsigned)(j * 32 + lane); }
                unsigned wm = redux_umax(lm);
                if (__uint_as_float(wm) < NMS_T) break;
                unsigned cand = (lm == wm) ? li : 0xFFFFFFFFu;
                unsigned wi = redux_umin(cand);
                float4 wb = R->sb[wi];
                float  a1 = R->sa[wi];
#pragma unroll
                for (int j = 0; j < 8; j++) {
                    if (act[j]) {
                        float ix1 = fmaxf(wb.x, bx[j].x), iy1 = fmaxf(wb.y, bx[j].y);
                        float ix2 = fminf(wb.z, bx[j].z), iy2 = fminf(wb.w, bx[j].w);
                        float iw = ix2 - ix1 + 1.0f, ih = iy2 - iy1 + 1.0f;
                        if (iw > 0.0f && ih > 0.0f) {
                            float inter = iw * ih;
                            float iou = inter / (a1 + a2[j] - inter + 1e-16f);
                            sc[j] *= expf(-(iou * iou) * 2.0f);
                            key[j] = __float_as_uint(sc[j]);
                        }
                    }
                    if ((unsigned)(j * 32 + lane) == wi) {
                        act[j] = false;
                        key[j] = 0u;
                        keptloc |= 1u << j;
                    }
                }
            }
#pragma unroll
            for (int j = 0; j < 8; j++)
                if (keptloc & (1u << j)) atomicOr(&R->skept[j], 1u << lane);
        }
    }
    __syncthreads();

    // warp 0: top-8 among kept by ORIGINAL score
    if (wid == 0) {
        unsigned key[8]; float so[8];
#pragma unroll
        for (int j = 0; j < 8; j++) {
            int slot = j * 32 + lane;
            bool k = (R->skept[j] >> lane) & 1u;
            float s = R->ssc[slot];
            so[j]  = s;
            key[j] = k ? __float_as_uint(s) : 0u;   // kept scores are > 0
        }
        float* ob = out + (size_t)b * 48;
        for (int k = 0; k < 8; k++) {
            unsigned lm = 0, li = 0;
#pragma unroll
            for (int j = 0; j < 8; j++)
                if (key[j] > lm) { lm = key[j]; li = (unsigned)(j * 32 + lane); }
            unsigned wm = redux_umax(lm);
            if (wm == 0u) {
                if (lane == 0) {
#pragma unroll
                    for (int i = 0; i < 6; i++) ob[k * 6 + i] = 0.0f;
                }
                continue;
            }
            unsigned cand = (lm == wm) ? li : 0xFFFFFFFFu;
            unsigned wi = redux_umin(cand);
#pragma unroll
            for (int j = 0; j < 8; j++) {
                if ((unsigned)(j * 32 + lane) == wi) {
                    int slot = j * 32 + lane;
                    float4 B = R->sb[slot];
                    ob[k * 6 + 0] = B.x;
                    ob[k * 6 + 1] = B.y;
                    ob[k * 6 + 2] = B.z;
                    ob[k * 6 + 3] = B.w;
                    ob[k * 6 + 4] = so[j];
                    ob[k * 6 + 5] = (float)R->scl[slot];
                    key[j] = 0u;
                }
            }
        }
    }
}

// =============================== fused kernel ===============================
__global__ __launch_bounds__(256, 4) void k_fused(
    const float* __restrict__ l0, const float* __restrict__ l1, const float* __restrict__ l2,
    float* __restrict__ out)
{
    __shared__ alignas(16) char smraw[
        sizeof(SmemScore) > sizeof(SmemRest) ? sizeof(SmemScore) : sizeof(SmemRest)];

    if (blockIdx.x < NB) {
        rest_block(blockIdx.x, out, reinterpret_cast<SmemRest*>(smraw));
    } else {
        score_block(blockIdx.x - NB, l0, l1, l2, reinterpret_cast<SmemScore*>(smraw));
    }
}

extern "C" void kernel_launch(void* const* d_in, const int* in_sizes, int n_in,
                              void* d_out, int out_size)
{
    const float* l0 = (const float*)d_in[0];
    const float* l1 = (const float*)d_in[1];
    const float* l2 = (const float*)d_in[2];
    float* out = (float*)d_out;

    k_fused<<<NB + NSBLK, 256>>>(l0, l1, l2, out);
}

// round 16
// speedup vs baseline: 1.0343x; 1.0343x over previous
#include <cuda_runtime.h>
#include <math.h>
#include <stdint.h>

#define NB    64
#define N0    1083     // 3*19*19
#define N1    4332     // 3*38*38
#define N2    17328    // 3*76*76
#define NTOT  22743
#define MCAND 256
#define NEGV  (-1e9f)
#define NMS_T 0.1f

#define RPB   256                         // records per score tile
#define NBLK0 ((NB * N0 + RPB - 1) / RPB) // 271 (last tile 192 records, even)
#define NBLK1 ((NB * N1) / RPB)           // 1083 (exact)
#define NBLK2 ((NB * N2) / RPB)           // 4332 (exact)
#define NSBLK (NBLK0 + NBLK1 + NBLK2)     // 5686 scoring tiles
#define GRIDP (148 * 5)                   // persistent scoring grid (all wave-1 resident)

// scratch (static __device__ — zero-init at load; counters reset per call by consumers)
__device__ int    g_done [NB];         // scoring tiles finished for image b
__device__ int    g_ncand[NB];
__device__ float  g_vsc [NB * NTOT];   // candidate scores per image
__device__ float4 g_cbx [NB * NTOT];   // candidate decoded boxes (xyxy, clamped)
__device__ float  g_car [NB * NTOT];   // candidate areas (+1 convention)
__device__ int    g_ccl [NB * NTOT];   // candidate class ids

__device__ __forceinline__ unsigned redux_umax(unsigned v) {
    unsigned r; asm("redux.sync.max.u32 %0, %1, 0xffffffff;" : "=r"(r) : "r"(v)); return r;
}
__device__ __forceinline__ unsigned redux_umin(unsigned v) {
    unsigned r; asm("redux.sync.min.u32 %0, %1, 0xffffffff;" : "=r"(r) : "r"(v)); return r;
}
__device__ __forceinline__ uint32_t smem_u32(const void* p) {
    return (uint32_t)__cvta_generic_to_shared(p);
}
__device__ __forceinline__ void mbar_wait(uint32_t mb, int parity) {
    asm volatile(
        "{\n\t"
        ".reg .pred P1;\n\t"
        "WAIT_%=:\n\t"
        "mbarrier.try_wait.parity.shared.b64 P1, [%0], %1;\n\t"
        "@P1 bra.uni DONE_%=;\n\t"
        "bra.uni WAIT_%=;\n\t"
        "DONE_%=:\n\t"
        "}"
        :: "r"(mb), "r"(parity) : "memory");
}

// geometry for flat per-image index n
__device__ __forceinline__ void geom(int n, int& gx, int& gy,
                                     float& stride, float& aw, float& ah)
{
    if (n < N0) {
        int a = n / 361, c = n - a * 361; gy = c / 19; gx = c - gy * 19;
        stride = 32.0f;
        aw = (a == 0) ? 116.0f : (a == 1) ? 156.0f : 373.0f;
        ah = (a == 0) ?  90.0f : (a == 1) ? 198.0f : 326.0f;
    } else if (n < N0 + N1) {
        int r = n - N0;
        int a = r / 1444, c = r - a * 1444; gy = c / 38; gx = c - gy * 38;
        stride = 16.0f;
        aw = (a == 0) ? 30.0f : (a == 1) ? 62.0f : 59.0f;
        ah = (a == 0) ? 61.0f : (a == 1) ? 45.0f : 119.0f;
    } else {
        int r = n - N0 - N1;
        int a = r / 5776, c = r - a * 5776; gy = c / 76; gx = c - gy * 76;
        stride = 8.0f;
        aw = (a == 0) ? 10.0f : (a == 1) ? 16.0f : 33.0f;
        ah = (a == 0) ? 13.0f : (a == 1) ? 30.0f : 23.0f;
    }
}

// scoring tiles of a level touching image b (RPB=256)
__device__ __forceinline__ int blocks_touching(int NL, int b) {
    int first = (b * NL) / RPB;
    int last  = ((b + 1) * NL - 1) / RPB;
    return last - first + 1;
}

// =============== Kernel 1: persistent scoring (score+compact+decode) ===============
__global__ __launch_bounds__(256, 6) void k_score_p(
    const float* __restrict__ l0, const float* __restrict__ l1, const float* __restrict__ l2)
{
    __shared__ alignas(16) float sm[RPB * 26];
    __shared__ alignas(8) unsigned long long mbar;
    __shared__ unsigned short s_list[RPB];
    __shared__ int s_cnt;

    uint32_t mb = smem_u32(&mbar);
    if (threadIdx.x == 0)
        asm volatile("mbarrier.init.shared.b64 [%0], 1;" :: "r"(mb) : "memory");
    __syncthreads();

    // release the PDL secondary immediately (all CTAs resident wave-1)
    asm volatile("griddepcontrol.launch_dependents;" ::: "memory");

    int phase = 0;
    for (int blk = blockIdx.x; blk < NSBLK; blk += GRIDP, phase ^= 1) {
        const float* in; int NL, OFF, base;
        if (blk < NBLK0)              { in = l0; NL = N0; OFF = 0;       base = blk * RPB; }
        else if (blk < NBLK0 + NBLK1) { in = l1; NL = N1; OFF = N0;      base = (blk - NBLK0) * RPB; }
        else                          { in = l2; NL = N2; OFF = N0 + N1; base = (blk - NBLK0 - NBLK1) * RPB; }

        int total = NB * NL;
        int nrec  = total - base; if (nrec > RPB) nrec = RPB;
        unsigned bytes = (unsigned)nrec * 104u;      // multiple of 16 (nrec even)
        const float* __restrict__ src = in + (size_t)base * 26;

        if (threadIdx.x == 0) {
            s_cnt = 0;
            asm volatile("mbarrier.arrive.expect_tx.shared.b64 _, [%0], %1;"
                         :: "r"(mb), "r"(bytes) : "memory");
            asm volatile("cp.async.bulk.shared::cta.global.mbarrier::complete_tx::bytes "
                         "[%0], [%1], %2, [%3];"
                         :: "r"(smem_u32(sm)), "l"(src), "r"(bytes), "r"(mb) : "memory");
        }
        mbar_wait(mb, phase);

        // ---- phase A: cheap conservative predicate + block compaction ----
        int t = threadIdx.x;
        unsigned lane = t & 31u;
        bool pass = false;
        if (t < nrec) {
            float p4 = sm[t * 26 + 4], p5 = sm[t * 26 + 5];
            // obj>=0.6 <=> p4>=ln(1.5); loc>=0.5 <=> p5>=0 (conservative; exact test below)
            pass = (p4 >= 0.405f) && (p5 >= -1e-6f);
        }
        unsigned mball = __ballot_sync(0xffffffffu, pass);
        int bs = 0;
        if (mball) {
            if (lane == 0) bs = atomicAdd(&s_cnt, __popc(mball));
            bs = __shfl_sync(0xffffffffu, bs, 0);
            if (pass) s_list[bs + __popc(mball & ((1u << lane) - 1u))] = (unsigned short)t;
        }
        __syncthreads();
        int cnt = s_cnt;

        int b_first = base / NL;
        int rem     = base - b_first * NL;
        int b_last  = (base + nrec - 1) / NL;

        // ---- phase B: dense exact scoring + decode on survivors only ----
        bool valid = false;
        float score = 0.0f;
        int bimg = 0, nloc = 0;
        float4 bx = make_float4(0.f, 0.f, 0.f, 0.f);
        int cc = 0;
        if (t < cnt) {
            int rec = s_list[t];
            const float* p = sm + rec * 26;
            float obj = 1.0f / (1.0f + expf(-p[4]));
            float loc = 1.0f / (1.0f + expf(-p[5]));
            float m = p[6];
#pragma unroll
            for (int i = 1; i < 20; i++) m = fmaxf(m, p[6 + i]);
            float s = 0.0f;
#pragma unroll
            for (int i = 0; i < 20; i++) s += expf(p[6 + i] - m);
            float conf = 1.0f / s;
            valid = (obj >= 0.6f) && (obj * conf >= 0.05f) && (loc >= 0.5f);
            score = sqrtf(obj * conf) * sqrtf(loc);
            int r_off = rec + rem;
            int over  = (r_off >= NL);
            bimg = b_first + over;
            nloc = r_off - (over ? NL : 0);

            if (valid) {
                int gx, gy; float stride, aw, ah;
                geom(OFF + nloc, gx, gy, stride, aw, ah);
                float cx = (1.0f / (1.0f + expf(-p[0])) + (float)gx) * stride;
                float cy = (1.0f / (1.0f + expf(-p[1])) + (float)gy) * stride;
                float w  = expf(p[2]) * aw;
                float h  = expf(p[3]) * ah;
                bx.x = fminf(fmaxf(cx - w * 0.5f, 0.0f), 608.0f);
                bx.y = fminf(fmaxf(cy - h * 0.5f, 0.0f), 608.0f);
                bx.z = fminf(fmaxf(cx + w * 0.5f, 0.0f), 608.0f);
                bx.w = fminf(fmaxf(cy + h * 0.5f, 0.0f), 608.0f);
                float best = p[6]; cc = 0;
#pragma unroll
                for (int i = 1; i < 20; i++) {
                    float v = p[6 + i];
                    if (v > best) { best = v; cc = i; }   // first max, like jnp.argmax
                }
            }
        }

        // warp-aggregated append (survivors in a warp span at most 2 images)
        int b0 = __shfl_sync(0xffffffffu, bimg, 0);
        bool same = (bimg == b0);
        unsigned m_same = __ballot_sync(0xffffffffu, valid && same);
        unsigned m_diff = __ballot_sync(0xffffffffu, valid && !same);
        int pos = -1, bw = 0;
        if (m_same) {
            int leader = __ffs(m_same) - 1;
            int base2 = 0;
            if ((int)lane == leader) base2 = atomicAdd(&g_ncand[b0], __popc(m_same));
            base2 = __shfl_sync(0xffffffffu, base2, leader);
            if (valid && same) { pos = base2 + __popc(m_same & ((1u << lane) - 1u)); bw = b0; }
        }
        if (m_diff) {
            int leader = __ffs(m_diff) - 1;
            int b1 = __shfl_sync(0xffffffffu, bimg, leader);
            int base2 = 0;
            if ((int)lane == leader) base2 = atomicAdd(&g_ncand[b1], __popc(m_diff));
            base2 = __shfl_sync(0xffffffffu, base2, leader);
            if (valid && !same) { pos = base2 + __popc(m_diff & ((1u << lane) - 1u)); bw = b1; }
        }
        if (pos >= 0) {
            size_t g = (size_t)bw * NTOT + pos;
            g_vsc[g] = score;
            g_cbx[g] = bx;
            g_car[g] = (bx.z - bx.x + 1.0f) * (bx.w - bx.y + 1.0f);
            g_ccl[g] = cc;
        }

        // release: all appends for this tile visible, then signal touched images
        __syncthreads();
        if (threadIdx.x == 0) {
            __threadfence();
            atomicAdd(&g_done[b_first], 1);
            if (b_last != b_first) atomicAdd(&g_done[b_last], 1);
        }
    }
}

// =============== Kernel 2: per-image consumer (PDL, spin on readiness) ===============
__global__ __launch_bounds__(256, 6) void k_rest64(float* __restrict__ out)
{
    int b = blockIdx.x, tid = threadIdx.x;
    const int nth = 256;
    int wid = tid >> 5, lane = tid & 31;

    __shared__ unsigned hist[2048];
    __shared__ unsigned wtot[8], wsuf[8];
    __shared__ int sh_chosen, sh_need, sh_abv, sh_nG, cntG, cntE;
    __shared__ unsigned lval[MCAND];
    __shared__ int      lidx[MCAND];
    __shared__ int      s_idx[MCAND];
    __shared__ float    ssc [MCAND];
    __shared__ float4   sb  [MCAND];
    __shared__ float    sa  [MCAND];
    __shared__ int      scl [MCAND];
    __shared__ int      cs  [20 * 32];
    __shared__ unsigned skept[8];

    // prologue overlaps production
    for (int i = tid; i < MCAND; i += nth) { s_idx[i] = -1; ssc[i] = NEGV; }
    for (int i = tid; i < 2048; i += nth) hist[i] = 0u;
    if (tid < 8) skept[tid] = 0u;
    if (tid == 0) { sh_need = MCAND; cntG = 0; cntE = 0; }

    // acquire: wait until every scoring tile touching image b has signaled
    int expected = blocks_touching(N0, b) + blocks_touching(N1, b) + blocks_touching(N2, b);
    if (tid == 0) {
        while (atomicAdd(&g_done[b], 0) < expected) __nanosleep(128);
        __threadfence();
    }
    __syncthreads();

    int n = g_ncand[b];
    const float* __restrict__ vs = g_vsc + (size_t)b * NTOT;
    __syncthreads();
    if (tid == 0) { g_ncand[b] = 0; g_done[b] = 0; }   // reset for next replay

    if (n <= MCAND) {
        for (int i = tid; i < n; i += nth) { s_idx[i] = i; ssc[i] = vs[i]; }
    } else {
        // 11-bit histogram over key bits [14:25): valid scores in [0.158,1.0]
        // => key bits [25:32) == 0x1F constant
        for (int i = tid; i < n; i += nth) {
            unsigned k = __float_as_uint(vs[i]);
            atomicAdd(&hist[(k >> 14) & 2047u], 1u);
        }
        __syncthreads();

        unsigned loc[8], tot = 0, ssum = 0;
        {
#pragma unroll
            for (int j = 7; j >= 0; j--) { tot += hist[tid * 8 + j]; loc[j] = tot; }
            ssum = tot;
#pragma unroll
            for (int off = 1; off < 32; off <<= 1) {
                unsigned o = __shfl_down_sync(0xffffffffu, ssum, off);
                if (lane + off < 32) ssum += o;
            }
            if (lane == 0) wtot[wid] = ssum;
        }
        __syncthreads();
        if (tid == 0) {
            unsigned run = 0;
            for (int w = 7; w >= 0; w--) { wsuf[w] = run; run += wtot[w]; }
        }
        __syncthreads();
        {
            unsigned above_t = wsuf[wid] + (ssum - tot);
#pragma unroll
            for (int j = 0; j < 8; j++) {
                unsigned sj  = above_t + loc[j];
                unsigned sj1 = (j == 7) ? above_t : above_t + loc[j + 1];
                if ((int)sj >= MCAND && (int)sj1 < MCAND) { sh_chosen = tid * 8 + j; sh_nG = (int)sj1; }
            }
        }
        __syncthreads();

        int nG      = sh_nG;
        int need2   = MCAND - nG;
        int cntbin  = (int)hist[sh_chosen];
        unsigned Pfull = (0x1Fu << 11) | (unsigned)sh_chosen;

        if (cntbin <= MCAND) {
            for (int i = tid; i < n; i += nth) {
                float v = vs[i];
                unsigned k = __float_as_uint(v);
                unsigned hi = k >> 14;
                if (hi > Pfull) {
                    int pos = atomicAdd(&cntG, 1);
                    s_idx[pos] = i; ssc[pos] = v;
                } else if (hi == Pfull) {
                    int e = atomicAdd(&cntE, 1);
                    lval[e] = k; lidx[e] = i;
                }
            }
            __syncthreads();
            if (wid == 0) {
                unsigned v0[8]; int id0[8];
#pragma unroll
                for (int j = 0; j < 8; j++) {
                    int p = lane + 32 * j;
                    v0[j]  = (p < cntbin) ? lval[p] : 0u;
                    id0[j] = (p < cntbin) ? lidx[p] : -1;
                }
                for (int r = 0; r < need2; r++) {
                    unsigned lm = v0[0];
#pragma unroll
                    for (int j = 1; j < 8; j++) lm = (v0[j] > lm) ? v0[j] : lm;
                    unsigned wm = redux_umax(lm);
                    unsigned li = 0xFFFFFFFFu;
                    if (lm == wm) {
#pragma unroll
                        for (int j = 7; j >= 0; j--)
                            if (v0[j] == wm) li = (unsigned)(lane + 32 * j);
                    }
                    unsigned wi = redux_umin(li);
                    if ((wi & 31u) == (unsigned)lane) {
                        int j = (int)(wi >> 5);
                        s_idx[nG + r] = id0[j];
                        ssc [nG + r] = __uint_as_float(v0[j]);
                        v0[j] = 0u;
                    }
                }
            }
        } else {
            // fallback (cntbin > 256, ~never): proven 4x8-bit radix
            unsigned prefix = 0;
            for (int p = 0; p < 4; p++) {
                if (tid < 256) hist[tid] = 0;
                __syncthreads();
                int shift = 24 - 8 * p;
                for (int i = tid; i < n; i += nth) {
                    unsigned k = __float_as_uint(vs[i]);
                    if (p == 0 || (k >> (shift + 8)) == prefix)
                        atomicAdd(&hist[(k >> shift) & 255u], 1u);
                }
                __syncthreads();
                int need = sh_need;
                if (tid < 32) {
                    unsigned lc[8]; unsigned tt = 0;
#pragma unroll
                    for (int j = 7; j >= 0; j--) { tt += hist[tid * 8 + j]; lc[j] = tt; }
                    unsigned s = tt;
#pragma unroll
                    for (int off = 1; off < 32; off <<= 1) {
                        unsigned o = __shfl_down_sync(0xffffffffu, s, off);
                        if (tid + off < 32) s += o;
                    }
                    unsigned above = s - tt;
#pragma unroll
                    for (int j = 0; j < 8; j++) {
                        unsigned sj  = above + lc[j];
                        unsigned sj1 = (j == 7) ? above : above + lc[j + 1];
                        if ((int)sj >= need && (int)sj1 < need) {
                            sh_chosen = tid * 8 + j; sh_abv = (int)sj1;
                        }
                    }
                }
                __syncthreads();
                if (tid == 0) sh_need = need - sh_abv;
                __syncthreads();
                prefix = (prefix << 8) | (unsigned)sh_chosen;
            }
            int need = sh_need;
            unsigned K = prefix;
            int nG2 = MCAND - need;
            for (int i = tid; i < n; i += nth) {
                float v = vs[i];
                unsigned k = __float_as_uint(v);
                int pos = -1;
                if (k > K)       pos = atomicAdd(&cntG, 1);
                else if (k == K) { int e = atomicAdd(&cntE, 1); if (e < need) pos = nG2 + e; }
                if (pos >= 0) { s_idx[pos] = i; ssc[pos] = v; }
            }
        }
    }
    __syncthreads();

    // gather precomputed decode data (24B per candidate)
    {
        int idx = s_idx[tid];
        float4 bx = make_float4(0.f, 0.f, 0.f, 0.f);
        float ar = 1.0f;
        int cc = -1;
        if (idx >= 0) {
            size_t g = (size_t)b * NTOT + idx;
            bx = g_cbx[g];
            ar = g_car[g];
            cc = g_ccl[g];
        }
        sb [tid] = bx;
        sa [tid] = ar;
        scl[tid] = cc;
    }
    __syncthreads();

    // per-class soft-NMS: 8 warps, warp w handles classes {w, w+8, w+16}
    // (kept set decomposes exactly per class; compaction puts one candidate/lane)
    for (int cl = wid; cl < 20; cl += 8) {
        int m = 0;
#pragma unroll
        for (int j = 0; j < 8; j++) {              // slots in increasing order
            int slot = j * 32 + lane;
            bool a = (scl[slot] == cl);
            unsigned mj = __ballot_sync(0xffffffffu, a);
            if (a) {
                int pos = m + __popc(mj & ((1u << lane) - 1u));
                if (pos < 32) cs[cl * 32 + pos] = slot;
            }
            m += __popc(mj);
        }
        __syncwarp();

        if (m > 0 && m <= 32) {
            bool active = lane < m;
            int slot = active ? cs[cl * 32 + lane] : 0;
            float4 B = sb[slot];
            float A2 = sa[slot];
            float sc = ssc[slot];
            unsigned key = active ? __float_as_uint(sc) : 0u;
            for (int it = 0; it < MCAND; it++) {
                unsigned wm = redux_umax(key);
                if (__uint_as_float(wm) < NMS_T) break;   // includes wm==0
                unsigned li = (key == wm) ? (unsigned)slot : 0xFFFFFFFFu;
                unsigned wi = redux_umin(li);             // first-index tie-break (exact)
                float4 wb = sb[wi];
                float  a1 = sa[wi];
                bool winner = active && ((unsigned)slot == wi);
                if (active) {
                    float ix1 = fmaxf(wb.x, B.x), iy1 = fmaxf(wb.y, B.y);
                    float ix2 = fminf(wb.z, B.z), iy2 = fminf(wb.w, B.w);
                    float iw = ix2 - ix1 + 1.0f, ih = iy2 - iy1 + 1.0f;
                    // inter==0 => decay=1.0 => sc unchanged (bitwise exact) — skip
                    if (iw > 0.0f && ih > 0.0f) {
                        float inter = iw * ih;
                        float iou = inter / (a1 + A2 - inter + 1e-16f);
                        sc *= expf(-(iou * iou) * 2.0f);   // exp(-iou^2 / 0.5)
                        key = __float_as_uint(sc);
                    }
                }
                if (winner) {
                    key = 0u; active = false;
                    atomicOr(&skept[slot >> 5], 1u << (slot & 31));
                }
            }
        } else if (m > 32) {
            // rare fallback: 8-slot register loop (exact)
            unsigned key[8]; float sc[8]; float4 bx[8]; float a2[8]; bool act[8];
#pragma unroll
            for (int j = 0; j < 8; j++) {
                int slot = j * 32 + lane;
                float s = ssc[slot];
                act[j] = (scl[slot] == cl);
                key[j] = act[j] ? __float_as_uint(s) : 0u;
                sc[j]  = s;
                bx[j]  = sb[slot];
                a2[j]  = sa[slot];
            }
            unsigned keptloc = 0;
            for (int it = 0; it < MCAND; it++) {
                unsigned lm = 0, li = 0;
#pragma unroll
                for (int j = 0; j < 8; j++)
                    if (key[j] > lm) { lm = key[j]; li = (unsigned)(j * 32 + lane); }
                unsigned wm = redux_umax(lm);
                if (__uint_as_float(wm) < NMS_T) break;
                unsigned cand = (lm == wm) ? li : 0xFFFFFFFFu;
                unsigned wi = redux_umin(cand);
                float4 wb = sb[wi];
                float  a1 = sa[wi];
#pragma unroll
                for (int j = 0; j < 8; j++) {
                    if (act[j]) {
                        float ix1 = fmaxf(wb.x, bx[j].x), iy1 = fmaxf(wb.y, bx[j].y);
                        float ix2 = fminf(wb.z, bx[j].z), iy2 = fminf(wb.w, bx[j].w);
                        float iw = ix2 - ix1 + 1.0f, ih = iy2 - iy1 + 1.0f;
                        if (iw > 0.0f && ih > 0.0f) {
                            float inter = iw * ih;
                            float iou = inter / (a1 + a2[j] - inter + 1e-16f);
                            sc[j] *= expf(-(iou * iou) * 2.0f);
                            key[j] = __float_as_uint(sc[j]);
                        }
                    }
                    if ((unsigned)(j * 32 + lane) == wi) {
                        act[j] = false;
                        key[j] = 0u;
                        keptloc |= 1u << j;
                    }
                }
            }
#pragma unroll
            for (int j = 0; j < 8; j++)
                if (keptloc & (1u << j)) atomicOr(&skept[j], 1u << lane);
        }
    }
    __syncthreads();

    // warp 0: top-8 among kept by ORIGINAL score
    if (wid == 0) {
        unsigned key[8]; float so[8];
#pragma unroll
        for (int j = 0; j < 8; j++) {
            int slot = j * 32 + lane;
            bool k = (skept[j] >> lane) & 1u;
            float s = ssc[slot];
            so[j]  = s;
            key[j] = k ? __float_as_uint(s) : 0u;   // kept scores are > 0
        }
        float* ob = out + (size_t)b * 48;
        for (int k = 0; k < 8; k++) {
            unsigned lm = 0, li = 0;
#pragma unroll
            for (int j = 0; j < 8; j++)
                if (key[j] > lm) { lm = key[j]; li = (unsigned)(j * 32 + lane); }
            unsigned wm = redux_umax(lm);
            if (wm == 0u) {
                if (lane == 0) {
#pragma unroll
                    for (int i = 0; i < 6; i++) ob[k * 6 + i] = 0.0f;
                }
                continue;
            }
            unsigned cand = (lm == wm) ? li : 0xFFFFFFFFu;
            unsigned wi = redux_umin(cand);
#pragma unroll
            for (int j = 0; j < 8; j++) {
                if ((unsigned)(j * 32 + lane) == wi) {
                    int slot = j * 32 + lane;
                    float4 B = sb[slot];
                    ob[k * 6 + 0] = B.x;
                    ob[k * 6 + 1] = B.y;
                    ob[k * 6 + 2] = B.z;
                    ob[k * 6 + 3] = B.w;
                    ob[k * 6 + 4] = so[j];
                    ob[k * 6 + 5] = (float)scl[slot];
                    key[j] = 0u;
                }
            }
        }
    }
}

extern "C" void kernel_launch(void* const* d_in, const int* in_sizes, int n_in,
                              void* d_out, int out_size)
{
    const float* l0 = (const float*)d_in[0];
    const float* l1 = (const float*)d_in[1];
    const float* l2 = (const float*)d_in[2];
    float* out = (float*)d_out;

    k_score_p<<<GRIDP, 256>>>(l0, l1, l2);

    // PDL secondary: released early by griddepcontrol.launch_dependents in primary;
    // consumers spin on per-image counters while scoring continues.
    cudaLaunchConfig_t cfg = {};
    cfg.gridDim  = dim3(NB, 1, 1);
    cfg.blockDim = dim3(256, 1, 1);
    cfg.dynamicSmemBytes = 0;
    cfg.stream = 0;
    cudaLaunchAttribute attrs[1];
    attrs[0].id = cudaLaunchAttributeProgrammaticStreamSerialization;
    attrs[0].val.programmaticStreamSerializationAllowed = 1;
    cfg.attrs = attrs;
    cfg.numAttrs = 1;
    cudaLaunchKernelEx(&cfg, k_rest64, out);
}

// round 17
// speedup vs baseline: 1.5460x; 1.4947x over previous
#include <cuda_runtime.h>
#include <math.h>
#include <stdint.h>

#define NB    64
#define N0    1083     // 3*19*19
#define N1    4332     // 3*38*38
#define N2    17328    // 3*76*76
#define NTOT  22743
#define MCAND 256
#define NEGV  (-1e9f)
#define NMS_T 0.1f
#define NSTG  4096     // smem key-staging capacity in k_rest

#define RPB   256                         // records per score block
#define NBLK0 ((NB * N0 + RPB - 1) / RPB) // 271 (last block 192 records, even)
#define NBLK1 ((NB * N1) / RPB)           // 1083 (exact)
#define NBLK2 ((NB * N2) / RPB)           // 4332 (exact)

// scratch (static __device__ — zero-initialized at load; g_ncand reset each call by k_rest)
__device__ int    g_ncand[NB];
__device__ float  g_vsc [NB * NTOT];   // candidate scores per image
__device__ float4 g_cbx [NB * NTOT];   // candidate decoded boxes (xyxy, clamped)
__device__ float  g_car [NB * NTOT];   // candidate areas (+1 convention)
__device__ int    g_ccl [NB * NTOT];   // candidate class ids

__device__ __forceinline__ unsigned redux_umax(unsigned v) {
    unsigned r; asm("redux.sync.max.u32 %0, %1, 0xffffffff;" : "=r"(r) : "r"(v)); return r;
}
__device__ __forceinline__ unsigned redux_umin(unsigned v) {
    unsigned r; asm("redux.sync.min.u32 %0, %1, 0xffffffff;" : "=r"(r) : "r"(v)); return r;
}
__device__ __forceinline__ uint32_t smem_u32(const void* p) {
    return (uint32_t)__cvta_generic_to_shared(p);
}
__device__ __forceinline__ void mbar_wait_p0(uint32_t mb) {
    asm volatile(
        "{\n\t"
        ".reg .pred P1;\n\t"
        "WAIT_%=:\n\t"
        "mbarrier.try_wait.parity.shared.b64 P1, [%0], 0;\n\t"
        "@P1 bra.uni DONE_%=;\n\t"
        "bra.uni WAIT_%=;\n\t"
        "DONE_%=:\n\t"
        "}"
        :: "r"(mb) : "memory");
}

// geometry for flat per-image index n: grid cell + stride + anchor (pixels)
__device__ __forceinline__ void geom(int n, int& gx, int& gy,
                                     float& stride, float& aw, float& ah)
{
    if (n < N0) {
        int a = n / 361, c = n - a * 361; gy = c / 19; gx = c - gy * 19;
        stride = 32.0f;
        aw = (a == 0) ? 116.0f : (a == 1) ? 156.0f : 373.0f;
        ah = (a == 0) ?  90.0f : (a == 1) ? 198.0f : 326.0f;
    } else if (n < N0 + N1) {
        int r = n - N0;
        int a = r / 1444, c = r - a * 1444; gy = c / 38; gx = c - gy * 38;
        stride = 16.0f;
        aw = (a == 0) ? 30.0f : (a == 1) ? 62.0f : 59.0f;
        ah = (a == 0) ? 61.0f : (a == 1) ? 45.0f : 119.0f;
    } else {
        int r = n - N0 - N1;
        int a = r / 5776, c = r - a * 5776; gy = c / 76; gx = c - gy * 76;
        stride = 8.0f;
        aw = (a == 0) ? 10.0f : (a == 1) ? 16.0f : 33.0f;
        ah = (a == 0) ? 13.0f : (a == 1) ? 30.0f : 23.0f;
    }
}

// ---------------- Kernel 1: fused score + compact + FULL DECODE (bulk-async staging) ----------------
__global__ __launch_bounds__(256, 6) void k_score_all(
    const float* __restrict__ l0, const float* __restrict__ l1, const float* __restrict__ l2)
{
    __shared__ alignas(16) float sm[RPB * 26];
    __shared__ alignas(8) unsigned long long mbar;
    __shared__ unsigned short s_list[RPB];
    __shared__ int s_cnt;

    int blk = blockIdx.x;
    const float* in; int NL, OFF, base;
    if (blk < NBLK0)              { in = l0; NL = N0; OFF = 0;       base = blk * RPB; }
    else if (blk < NBLK0 + NBLK1) { in = l1; NL = N1; OFF = N0;      base = (blk - NBLK0) * RPB; }
    else                          { in = l2; NL = N2; OFF = N0 + N1; base = (blk - NBLK0 - NBLK1) * RPB; }

    int total = NB * NL;
    int nrec  = total - base; if (nrec > RPB) nrec = RPB;
    unsigned bytes = (unsigned)nrec * 104u;      // multiple of 16 (nrec even)
    const float* __restrict__ src = in + (size_t)base * 26;

    uint32_t mb = smem_u32(&mbar);
    if (threadIdx.x == 0) {
        s_cnt = 0;
        asm volatile("mbarrier.init.shared.b64 [%0], 1;" :: "r"(mb) : "memory");
    }
    __syncthreads();
    if (threadIdx.x == 0) {
        asm volatile("mbarrier.arrive.expect_tx.shared.b64 _, [%0], %1;"
                     :: "r"(mb), "r"(bytes) : "memory");
        asm volatile("cp.async.bulk.shared::cta.global.mbarrier::complete_tx::bytes "
                     "[%0], [%1], %2, [%3];"
                     :: "r"(smem_u32(sm)), "l"(src), "r"(bytes), "r"(mb) : "memory");
    }
    mbar_wait_p0(mb);

    // ---- phase A: cheap conservative predicate + block compaction ----
    int t = threadIdx.x;
    unsigned lane = t & 31u;
    bool pass = false;
    if (t < nrec) {
        float p4 = sm[t * 26 + 4], p5 = sm[t * 26 + 5];
        // obj>=0.6 <=> p4>=ln(1.5); loc>=0.5 <=> p5>=0 (conservative; exact test in phase B)
        pass = (p4 >= 0.405f) && (p5 >= -1e-6f);
    }
    unsigned mball = __ballot_sync(0xffffffffu, pass);
    int bs = 0;
    if (mball) {
        if (lane == 0) bs = atomicAdd(&s_cnt, __popc(mball));
        bs = __shfl_sync(0xffffffffu, bs, 0);
        if (pass) s_list[bs + __popc(mball & ((1u << lane) - 1u))] = (unsigned short)t;
    }
    __syncthreads();
    int cnt = s_cnt;

    int b_first = base / NL;
    int rem     = base - b_first * NL;

    // ---- phase B: dense exact scoring + full decode on survivors only ----
    bool valid = false;
    float score = 0.0f;
    int bimg = 0, nloc = 0;
    float4 bx = make_float4(0.f, 0.f, 0.f, 0.f);
    int cc = 0;
    if (t < cnt) {
        int rec = s_list[t];
        const float* p = sm + rec * 26;
        float obj = 1.0f / (1.0f + expf(-p[4]));
        float loc = 1.0f / (1.0f + expf(-p[5]));
        float m = p[6];
#pragma unroll
        for (int i = 1; i < 20; i++) m = fmaxf(m, p[6 + i]);
        float s = 0.0f;
#pragma unroll
        for (int i = 0; i < 20; i++) s += expf(p[6 + i] - m);
        float conf = 1.0f / s;
        valid = (obj >= 0.6f) && (obj * conf >= 0.05f) && (loc >= 0.5f);
        score = sqrtf(obj * conf) * sqrtf(loc);
        int r_off = rec + rem;
        int over  = (r_off >= NL);
        bimg = b_first + over;
        nloc = r_off - (over ? NL : 0);

        if (valid) {
            int gx, gy; float stride, aw, ah;
            geom(OFF + nloc, gx, gy, stride, aw, ah);
            float cx = (1.0f / (1.0f + expf(-p[0])) + (float)gx) * stride;
            float cy = (1.0f / (1.0f + expf(-p[1])) + (float)gy) * stride;
            float w  = expf(p[2]) * aw;
            float h  = expf(p[3]) * ah;
            bx.x = fminf(fmaxf(cx - w * 0.5f, 0.0f), 608.0f);
            bx.y = fminf(fmaxf(cy - h * 0.5f, 0.0f), 608.0f);
            bx.z = fminf(fmaxf(cx + w * 0.5f, 0.0f), 608.0f);
            bx.w = fminf(fmaxf(cy + h * 0.5f, 0.0f), 608.0f);
            float best = p[6]; cc = 0;
#pragma unroll
            for (int i = 1; i < 20; i++) {
                float v = p[6 + i];
                if (v > best) { best = v; cc = i; }   // first max, like jnp.argmax
            }
        }
    }

    // warp-aggregated append (survivors in a warp span at most 2 images)
    int b0 = __shfl_sync(0xffffffffu, bimg, 0);
    bool same = (bimg == b0);
    unsigned m_same = __ballot_sync(0xffffffffu, valid && same);
    unsigned m_diff = __ballot_sync(0xffffffffu, valid && !same);
    int pos = -1, bw = 0;
    if (m_same) {
        int leader = __ffs(m_same) - 1;
        int base2 = 0;
        if ((int)lane == leader) base2 = atomicAdd(&g_ncand[b0], __popc(m_same));
        base2 = __shfl_sync(0xffffffffu, base2, leader);
        if (valid && same) { pos = base2 + __popc(m_same & ((1u << lane) - 1u)); bw = b0; }
    }
    if (m_diff) {
        int leader = __ffs(m_diff) - 1;
        int b1 = __shfl_sync(0xffffffffu, bimg, leader);
        int base2 = 0;
        if ((int)lane == leader) base2 = atomicAdd(&g_ncand[b1], __popc(m_diff));
        base2 = __shfl_sync(0xffffffffu, base2, leader);
        if (valid && !same) { pos = base2 + __popc(m_diff & ((1u << lane) - 1u)); bw = b1; }
    }
    if (pos >= 0) {
        size_t g = (size_t)bw * NTOT + pos;
        g_vsc[g] = score;
        g_cbx[g] = bx;
        g_car[g] = (bx.z - bx.x + 1.0f) * (bx.w - bx.y + 1.0f);
        g_ccl[g] = cc;
    }
}

// ---------------- Kernel 2: per-image top-256 + soft-NMS + top-8 (PDL) ----------------
__global__ __launch_bounds__(640) void k_rest(float* __restrict__ out)
{
    int b = blockIdx.x, tid = threadIdx.x;
    const int nth = 640;
    int wid = tid >> 5, lane = tid & 31;

    __shared__ unsigned skeys[NSTG];    // staged score keys (avoid 2nd global sweep)
    __shared__ unsigned hist[2048];
    __shared__ unsigned wtot[8], wsuf[8];
    __shared__ int sh_chosen, sh_need, sh_abv, sh_nG, cntG, cntE;
    __shared__ unsigned lval[MCAND];
    __shared__ int      lidx[MCAND];
    __shared__ int      s_idx[MCAND];   // candidate POSITION in per-image arrays (-1 empty)
    __shared__ float    ssc  [MCAND];
    __shared__ float4   sb   [MCAND];
    __shared__ float    sa   [MCAND];
    __shared__ int      scl  [MCAND];
    __shared__ int      cs   [20 * 32];
    __shared__ unsigned skept[8];

    // ---- prologue (overlaps primary kernel via PDL) ----
    for (int i = tid; i < MCAND; i += nth) { s_idx[i] = -1; ssc[i] = NEGV; }
    for (int i = tid; i < 2048; i += nth) hist[i] = 0u;
    if (tid < 8) skept[tid] = 0u;
    if (tid == 0) { sh_need = MCAND; cntG = 0; cntE = 0; }

    cudaGridDependencySynchronize();      // wait for k_score_all's writes

    int n = g_ncand[b];
    const float* __restrict__ vs = g_vsc + (size_t)b * NTOT;
    __syncthreads();                      // reads of g_ncand[b] done + smem init visible
    if (tid == 0) g_ncand[b] = 0;         // reset for next call (ordered after reads)

    if (n <= MCAND) {
        for (int i = tid; i < n; i += nth) { s_idx[i] = i; ssc[i] = vs[i]; }
    } else {
        bool staged = (n <= NSTG);
        // ---- pass A: 11-bit histogram over key bits [14:25), staging keys in smem ----
        // valid scores lie in [0.158, 1.0] => key bits [25:32) == 0x1F constant
        for (int i = tid; i < n; i += nth) {
            unsigned k = __float_as_uint(vs[i]);
            if (staged) skeys[i] = k;
            atomicAdd(&hist[(k >> 14) & 2047u], 1u);
        }
        __syncthreads();

        unsigned loc[8], tot = 0, ssum = 0;
        if (tid < 256) {
#pragma unroll
            for (int j = 7; j >= 0; j--) { tot += hist[tid * 8 + j]; loc[j] = tot; }
            ssum = tot;
#pragma unroll
            for (int off = 1; off < 32; off <<= 1) {
                unsigned o = __shfl_down_sync(0xffffffffu, ssum, off);
                if (lane + off < 32) ssum += o;
            }
            if (lane == 0) wtot[wid] = ssum;
        }
        __syncthreads();
        if (tid == 0) {
            unsigned run = 0;
            for (int w = 7; w >= 0; w--) { wsuf[w] = run; run += wtot[w]; }
        }
        __syncthreads();
        if (tid < 256) {
            unsigned above_t = wsuf[wid] + (ssum - tot);
#pragma unroll
            for (int j = 0; j < 8; j++) {
                unsigned sj  = above_t + loc[j];
                unsigned sj1 = (j == 7) ? above_t : above_t + loc[j + 1];
                if ((int)sj >= MCAND && (int)sj1 < MCAND) { sh_chosen = tid * 8 + j; sh_nG = (int)sj1; }
            }
        }
        __syncthreads();

        int nG      = sh_nG;
        int need2   = MCAND - nG;
        int cntbin  = (int)hist[sh_chosen];
        unsigned Pfull = (0x1Fu << 11) | (unsigned)sh_chosen;

        if (cntbin <= MCAND) {
            // ---- pass B: distribution sweep over smem-staged keys (or global fallback) ----
            for (int i = tid; i < n; i += nth) {
                unsigned k = staged ? skeys[i] : __float_as_uint(vs[i]);
                unsigned hi = k >> 14;
                if (hi > Pfull) {
                    int pos = atomicAdd(&cntG, 1);
                    s_idx[pos] = i; ssc[pos] = __uint_as_float(k);
                } else if (hi == Pfull) {
                    int e = atomicAdd(&cntE, 1);
                    lval[e] = k; lidx[e] = i;
                }
            }
            __syncthreads();
            // ---- warp 0: exact top-need2 extraction from the small tie-bin list ----
            if (wid == 0) {
                unsigned v0[8]; int id0[8];
#pragma unroll
                for (int j = 0; j < 8; j++) {
                    int p = lane + 32 * j;
                    v0[j]  = (p < cntbin) ? lval[p] : 0u;
                    id0[j] = (p < cntbin) ? lidx[p] : -1;
                }
                for (int r = 0; r < need2; r++) {
                    unsigned lm = v0[0];
#pragma unroll
                    for (int j = 1; j < 8; j++) lm = (v0[j] > lm) ? v0[j] : lm;
                    unsigned wm = redux_umax(lm);
                    unsigned li = 0xFFFFFFFFu;
                    if (lm == wm) {
#pragma unroll
                        for (int j = 7; j >= 0; j--)
                            if (v0[j] == wm) li = (unsigned)(lane + 32 * j);
                    }
                    unsigned wi = redux_umin(li);
                    if ((wi & 31u) == (unsigned)lane) {
                        int j = (int)(wi >> 5);
                        s_idx[nG + r] = id0[j];
                        ssc  [nG + r] = __uint_as_float(v0[j]);
                        v0[j] = 0u;
                    }
                }
            }
        } else {
            // fallback (cntbin > 256, ~never): proven 4x8-bit radix
            unsigned prefix = 0;
            for (int p = 0; p < 4; p++) {
                if (tid < 256) hist[tid] = 0;
                __syncthreads();
                int shift = 24 - 8 * p;
                for (int i = tid; i < n; i += nth) {
                    unsigned k = staged ? skeys[i] : __float_as_uint(vs[i]);
                    if (p == 0 || (k >> (shift + 8)) == prefix)
                        atomicAdd(&hist[(k >> shift) & 255u], 1u);
                }
                __syncthreads();
                int need = sh_need;
                if (tid < 32) {
                    unsigned lc[8]; unsigned tt = 0;
#pragma unroll
                    for (int j = 7; j >= 0; j--) { tt += hist[tid * 8 + j]; lc[j] = tt; }
                    unsigned s = tt;
#pragma unroll
                    for (int off = 1; off < 32; off <<= 1) {
                        unsigned o = __shfl_down_sync(0xffffffffu, s, off);
                        if (tid + off < 32) s += o;
                    }
                    unsigned above = s - tt;
#pragma unroll
                    for (int j = 0; j < 8; j++) {
                        unsigned sj  = above + lc[j];
                        unsigned sj1 = (j == 7) ? above : above + lc[j + 1];
                        if ((int)sj >= need && (int)sj1 < need) {
                            sh_chosen = tid * 8 + j; sh_abv = (int)sj1;
                        }
                    }
                }
                __syncthreads();
                if (tid == 0) sh_need = need - sh_abv;
                __syncthreads();
                prefix = (prefix << 8) | (unsigned)sh_chosen;
            }
            int need = sh_need;
            unsigned K = prefix;
            int nG2 = MCAND - need;
            for (int i = tid; i < n; i += nth) {
                unsigned k = staged ? skeys[i] : __float_as_uint(vs[i]);
                int pos = -1;
                if (k > K)       pos = atomicAdd(&cntG, 1);
                else if (k == K) { int e = atomicAdd(&cntE, 1); if (e < need) pos = nG2 + e; }
                if (pos >= 0) { s_idx[pos] = i; ssc[pos] = __uint_as_float(k); }
            }
        }
    }
    __syncthreads();

    // ---- gather precomputed decode data (threads 0..255; 24B per candidate) ----
    if (tid < MCAND) {
        int idx = s_idx[tid];
        float4 bx = make_float4(0.f, 0.f, 0.f, 0.f);
        float ar = 1.0f;
        int cc = -1;
        if (idx >= 0) {
            size_t g = (size_t)b * NTOT + idx;
            bx = g_cbx[g];
            ar = g_car[g];
            cc = g_ccl[g];
        }
        sb [tid] = bx;
        sa [tid] = ar;
        scl[tid] = cc;
    }
    __syncthreads();

    // ---- per-class soft-NMS: warp `wid` handles class `wid` (20 warps) ----
    // Soft-NMS only decays same-class scores and 256 steps drain every candidate,
    // so the kept set decomposes exactly per class. Per-class compaction puts one
    // candidate per lane (classes average ~13 of 256 slots).
    {
        int cl = wid;
        int m = 0;
#pragma unroll
        for (int j = 0; j < 8; j++) {              // slots in increasing order
            int slot = j * 32 + lane;
            bool a = (scl[slot] == cl);
            unsigned mj = __ballot_sync(0xffffffffu, a);
            if (a) {
                int pos = m + __popc(mj & ((1u << lane) - 1u));
                if (pos < 32) cs[cl * 32 + pos] = slot;
            }
            m += __popc(mj);
        }
        __syncwarp();

        if (m > 0 && m <= 32) {
            bool active = lane < m;
            int slot = active ? cs[cl * 32 + lane] : 0;
            float4 B = sb[slot];
            float A2 = sa[slot];
            float sc = ssc[slot];
            unsigned key = active ? __float_as_uint(sc) : 0u;
            for (int it = 0; it < MCAND; it++) {
                unsigned wm = redux_umax(key);
                if (__uint_as_float(wm) < NMS_T) break;   // includes wm==0
                unsigned li = (key == wm) ? (unsigned)slot : 0xFFFFFFFFu;
                unsigned wi = redux_umin(li);             // first-index tie-break (exact)
                float4 wb = sb[wi];
                float  a1 = sa[wi];
                bool winner = active && ((unsigned)slot == wi);
                if (active) {
                    float ix1 = fmaxf(wb.x, B.x), iy1 = fmaxf(wb.y, B.y);
                    float ix2 = fminf(wb.z, B.z), iy2 = fminf(wb.w, B.w);
                    float iw = ix2 - ix1 + 1.0f, ih = iy2 - iy1 + 1.0f;
                    // inter==0 => decay=1.0 => sc unchanged (bitwise exact) — skip
                    if (iw > 0.0f && ih > 0.0f) {
                        float inter = iw * ih;
                        float iou = inter / (a1 + A2 - inter + 1e-16f);
                        sc *= expf(-(iou * iou) * 2.0f);   // exp(-iou^2 / 0.5)
                        key = __float_as_uint(sc);
                    }
                }
                if (winner) {
                    key = 0u; active = false;
                    atomicOr(&skept[slot >> 5], 1u << (slot & 31));
                }
            }
        } else if (m > 32) {
            // rare fallback: 8-slot register loop (exact)
            unsigned key[8]; float sc[8]; float4 bx[8]; float a2[8]; bool act[8];
#pragma unroll
            for (int j = 0; j < 8; j++) {
                int slot = j * 32 + lane;
                float s = ssc[slot];
                act[j] = (scl[slot] == cl);
                key[j] = act[j] ? __float_as_uint(s) : 0u;
                sc[j]  = s;
                bx[j]  = sb[slot];
                a2[j]  = sa[slot];
            }
            unsigned keptloc = 0;
            for (int it = 0; it < MCAND; it++) {
                unsigned lm = 0, li = 0;
#pragma unroll
                for (int j = 0; j < 8; j++)
                    if (key[j] > lm) { lm = key[j]; li = (unsigned)(j * 32 + lane); }
                unsigned wm = redux_umax(lm);
                if (__uint_as_float(wm) < NMS_T) break;
                unsigned cand = (lm == wm) ? li : 0xFFFFFFFFu;
                unsigned wi = redux_umin(cand);
                float4 wb = sb[wi];
                float  a1 = sa[wi];
#pragma unroll
                for (int j = 0; j < 8; j++) {
                    if (act[j]) {
                        float ix1 = fmaxf(wb.x, bx[j].x), iy1 = fmaxf(wb.y, bx[j].y);
                        float ix2 = fminf(wb.z, bx[j].z), iy2 = fminf(wb.w, bx[j].w);
                        float iw = ix2 - ix1 + 1.0f, ih = iy2 - iy1 + 1.0f;
                        if (iw > 0.0f && ih > 0.0f) {
                            float inter = iw * ih;
                            float iou = inter / (a1 + a2[j] - inter + 1e-16f);
                            sc[j] *= expf(-(iou * iou) * 2.0f);
                            key[j] = __float_as_uint(sc[j]);
                        }
                    }
                    if ((unsigned)(j * 32 + lane) == wi) {
                        act[j] = false;
                        key[j] = 0u;
                        keptloc |= 1u << j;
                    }
                }
            }
#pragma unroll
            for (int j = 0; j < 8; j++)
                if (keptloc & (1u << j)) atomicOr(&skept[j], 1u << lane);
        }
    }
    __syncthreads();

    // ---- warp 0: top-8 among kept by ORIGINAL score ----
    if (wid == 0) {
        unsigned key[8]; float so[8];
#pragma unroll
        for (int j = 0; j < 8; j++) {
            int slot = j * 32 + lane;
            bool k = (skept[j] >> lane) & 1u;
            float s = ssc[slot];
            so[j]  = s;
            key[j] = k ? __float_as_uint(s) : 0u;   // kept scores are > 0
        }
        float* ob = out + (size_t)b * 48;
        for (int k = 0; k < 8; k++) {
            unsigned lm = 0, li = 0;
#pragma unroll
            for (int j = 0; j < 8; j++)
                if (key[j] > lm) { lm = key[j]; li = (unsigned)(j * 32 + lane); }
            unsigned wm = redux_umax(lm);
            if (wm == 0u) {
                if (lane == 0) {
#pragma unroll
                    for (int i = 0; i < 6; i++) ob[k * 6 + i] = 0.0f;
                }
                continue;
            }
            unsigned cand = (lm == wm) ? li : 0xFFFFFFFFu;
            unsigned wi = redux_umin(cand);
#pragma unroll
            for (int j = 0; j < 8; j++) {
                if ((unsigned)(j * 32 + lane) == wi) {
                    int slot = j * 32 + lane;
                    float4 B = sb[slot];
                    ob[k * 6 + 0] = B.x;
                    ob[k * 6 + 1] = B.y;
                    ob[k * 6 + 2] = B.z;
                    ob[k * 6 + 3] = B.w;
                    ob[k * 6 + 4] = so[j];
                    ob[k * 6 + 5] = (float)scl[slot];
                    key[j] = 0u;
                }
            }
        }
    }
}

extern "C" void kernel_launch(void* const* d_in, const int* in_sizes, int n_in,
                              void* d_out, int out_size)
{
    const float* l0 = (const float*)d_in[0];
    const float* l1 = (const float*)d_in[1];
    const float* l2 = (const float*)d_in[2];
    float* out = (float*)d_out;

    k_score_all<<<NBLK0 + NBLK1 + NBLK2, 256>>>(l0, l1, l2);

    // k_rest with Programmatic Dependent Launch: prologue overlaps k_score tail.
    cudaLaunchConfig_t cfg = {};
    cfg.gridDim  = dim3(NB, 1, 1);
    cfg.blockDim = dim3(640, 1, 1);
    cfg.dynamicSmemBytes = 0;
    cfg.stream = 0;
    cudaLaunchAttribute attrs[1];
    attrs[0].id = cudaLaunchAttributeProgrammaticStreamSerialization;
    attrs[0].val.programmaticStreamSerializationAllowed = 1;
    cfg.attrs = attrs;
    cfg.numAttrs = 1;
    cudaLaunchKernelEx(&cfg, k_rest, out);
}